// round 8
// baseline (speedup 1.0000x reference)
#include <cuda_runtime.h>
#include <cstdint>
#include <cstddef>

// ---------------- problem-size caps (from reference) ----------------
#define NMAXA  25000
#define EMAXE  800000
#define EAMAXE 300000
#define TMAXT  1600000

// ---------------- static device scratch (no allocations) ----------------
__device__ float g_rb  [EMAXE  * 8];              // radial basis per edge
__device__ float g_rba [EAMAXE * 8];              // radial basis per angle-edge
__device__ float g_da0 [EAMAXE * 8];              // rba @ W_da0
__device__ float g_da1 [EAMAXE * 8];              // rba @ W_da1
__device__ float g_sdst[NMAXA  * 32];             // s[:,64:96] per atom (per layer)
__device__ float g_ei0 [(size_t)NMAXA * 376];     // layer-0 concat features
__device__ float g_ei1 [(size_t)NMAXA * 616];     // layer-1 concat features
__device__ float g_xi  [(size_t)NMAXA * 256];     // atom state after layer 0
__device__ int   g_etmp[NMAXA];
__device__ int   g_ttmp[NMAXA];
__device__ int   g_ecnt[NMAXA + 1];
__device__ int   g_tcnt[NMAXA + 1];
__device__ int   g_ecur[NMAXA];
__device__ int   g_tcur[NMAXA];
__device__ int   g_ecsr[EMAXE];
__device__ int   g_tcsr[TMAXT];

#define PI_F 3.14159265358979323846f

// ---------------- helpers ----------------
__device__ __forceinline__ unsigned long long ffma2(unsigned long long a,
                                                    unsigned long long b,
                                                    unsigned long long c) {
    unsigned long long d;
    asm("fma.rn.f32x2 %0, %1, %2, %3;" : "=l"(d) : "l"(a), "l"(b), "l"(c));
    return d;
}

__device__ __forceinline__ float tssr2f(float x) {
    float ax = fabsf(x);
    if (ax <= 1.0f) return x;
    return copysignf(2.0f * sqrtf(ax) - 1.0f, x);
}

// ---------------- radial bessel basis * switch (per element) ----------------
__device__ __forceinline__ void radial_one(const float* __restrict__ dist,
                                           const float* __restrict__ sw,
                                           float* __restrict__ out, int e, float rc) {
    float r = dist[e], w = sw[e];
    float x = (PI_F / rc) * r;
    float s, c;
    sincosf(x, &s, &c);
    float norm = sqrtf(2.0f / rc) * w / r;
    float c2 = 2.0f * c;
    float o[8];
    float sk = s, skm = 0.0f;
#pragma unroll
    for (int k = 0; k < 8; ++k) {
        o[k] = sk * norm;
        float nx = c2 * sk - skm;
        skm = sk; sk = nx;
    }
    float4* dst = (float4*)(out + (size_t)e * 8);
    dst[0] = make_float4(o[0], o[1], o[2], o[3]);
    dst[1] = make_float4(o[4], o[5], o[6], o[7]);
}

// ---------------- s0 body: species_table[species] @ W_si0 ----------------
__device__ __forceinline__ void s0_body(const int* __restrict__ species,
                                        const float* __restrict__ table,
                                        const float* __restrict__ Wsi,
                                        int n, int blk) {
    __shared__ __align__(16) float Ws[16 * 96];
    for (int i = threadIdx.x; i < 16 * 96; i += 256) Ws[i] = Wsi[i];
    __syncthreads();
    int a = blk * 256 + threadIdx.x;
    if (a >= n) return;
    int sp = species[a];
    float* er = g_ei0 + (size_t)a * 376;
    float xv[16];
#pragma unroll
    for (int q = 0; q < 4; ++q) {
        float4 t = ((const float4*)(table + (size_t)sp * 16))[q];
        xv[4 * q + 0] = t.x; xv[4 * q + 1] = t.y; xv[4 * q + 2] = t.z; xv[4 * q + 3] = t.w;
        ((float4*)er)[q] = t;
    }
    float acc[96];
#pragma unroll
    for (int j = 0; j < 96; ++j) acc[j] = 0.0f;
#pragma unroll
    for (int k = 0; k < 16; ++k) {
        float av = xv[k];
#pragma unroll
        for (int q = 0; q < 24; ++q) {
            float4 w = *(const float4*)&Ws[k * 96 + 4 * q];
            acc[4 * q + 0] += av * w.x;
            acc[4 * q + 1] += av * w.y;
            acc[4 * q + 2] += av * w.z;
            acc[4 * q + 3] += av * w.w;
        }
    }
#pragma unroll
    for (int q = 0; q < 16; ++q)
        ((float4*)(er + 16))[q] = make_float4(acc[4 * q], acc[4 * q + 1], acc[4 * q + 2], acc[4 * q + 3]);
#pragma unroll
    for (int q = 0; q < 8; ++q)
        ((float4*)(g_sdst + (size_t)a * 32))[q] =
            make_float4(acc[64 + 4 * q], acc[65 + 4 * q], acc[66 + 4 * q], acc[67 + 4 * q]);
}

// ---------------- zero counters (must precede fused hist) ----------------
__global__ void k_zero(int n) {
    int i = blockIdx.x * blockDim.x + threadIdx.x;
    if (i < n) { g_etmp[i] = 0; g_ttmp[i] = 0; }
}

// ---------------- fused prep1: s0 + rb + rba + hist_e + hist_t ----------------
__global__ __launch_bounds__(256) void k_prep1(
        const int* __restrict__ species, const float* __restrict__ table,
        const float* __restrict__ Wsi0,
        const float* __restrict__ dist, const float* __restrict__ sw,
        const float* __restrict__ dist_a, const float* __restrict__ sw_a,
        const int* __restrict__ esrc, const int* __restrict__ ca,
        int n_atoms, int ne, int nea, int nt,
        int gs, int ge, int ga, int ge2) {
    int b = blockIdx.x;
    if (b < gs) {
        s0_body(species, table, Wsi0, n_atoms, b);
    } else if (b < gs + ge) {
        int e = (b - gs) * 256 + threadIdx.x;
        if (e < ne) radial_one(dist, sw, g_rb, e, 5.0f);
    } else if (b < gs + ge + ga) {
        int e = (b - gs - ge) * 256 + threadIdx.x;
        if (e < nea) radial_one(dist_a, sw_a, g_rba, e, 3.5f);
    } else if (b < gs + ge + ga + ge2) {
        int i = (b - gs - ge - ga) * 256 + threadIdx.x;
        if (i < ne) atomicAdd(&g_etmp[esrc[i]], 1);
    } else {
        int i = (b - gs - ge - ga - ge2) * 256 + threadIdx.x;
        if (i < nt) atomicAdd(&g_ttmp[ca[i]], 1);
    }
}

// ---------------- both scans in one launch (shfl-based, 2 blocks) ----------------
__device__ __forceinline__ void scan_body(const int* __restrict__ cnt,
                                          int* __restrict__ offs,
                                          int* __restrict__ cur, int n) {
    __shared__ int wsum[32];
    __shared__ int s_carry;
    int tid = threadIdx.x, lane = tid & 31, wid = tid >> 5;
    if (tid == 0) s_carry = 0;
    __syncthreads();
    for (int base = 0; base < n; base += 1024) {
        int v = (base + tid < n) ? cnt[base + tid] : 0;
        int x = v;
#pragma unroll
        for (int o = 1; o < 32; o <<= 1) {
            int t = __shfl_up_sync(0xffffffffu, x, o);
            if (lane >= o) x += t;
        }
        if (lane == 31) wsum[wid] = x;
        __syncthreads();
        if (wid == 0) {
            int y = wsum[lane];
#pragma unroll
            for (int o = 1; o < 32; o <<= 1) {
                int t = __shfl_up_sync(0xffffffffu, y, o);
                if (lane >= o) y += t;
            }
            wsum[lane] = y;
        }
        __syncthreads();
        int woff = wid ? wsum[wid - 1] : 0;
        int carry = s_carry;
        int total = wsum[31];
        int excl = carry + woff + x - v;
        if (base + tid < n) { offs[base + tid] = excl; cur[base + tid] = excl; }
        __syncthreads();
        if (tid == 0) s_carry = carry + total;
        __syncthreads();
    }
    if (tid == 0) offs[n] = s_carry;
}

__global__ void k_scan2(int n) {
    if (blockIdx.x == 0) scan_body(g_etmp, g_ecnt, g_ecur, n);
    else                 scan_body(g_ttmp, g_tcnt, g_tcur, n);
}

// ---------------- fused prep 2: scatter_e + scatter_t + da0 + da1 (R4 form) ----------------
__device__ __forceinline__ void da_one(const float* __restrict__ Wsh,
                                       float* __restrict__ out, int e) {
    float4 r0 = *(const float4*)(g_rba + (size_t)e * 8);
    float4 r1 = *(const float4*)(g_rba + (size_t)e * 8 + 4);
    float r[8] = { r0.x, r0.y, r0.z, r0.w, r1.x, r1.y, r1.z, r1.w };
    float o[8];
#pragma unroll
    for (int j = 0; j < 8; ++j) {
        float s = 0.0f;
#pragma unroll
        for (int k = 0; k < 8; ++k) s += r[k] * Wsh[k * 8 + j];
        o[j] = s;
    }
    float4* dst = (float4*)(out + (size_t)e * 8);
    dst[0] = make_float4(o[0], o[1], o[2], o[3]);
    dst[1] = make_float4(o[4], o[5], o[6], o[7]);
}

__global__ void k_prep2(const int* __restrict__ esrc, const int* __restrict__ ca,
                        const float* __restrict__ Wda0, const float* __restrict__ Wda1,
                        int ne, int nt, int nea, int ge, int gt, int ga) {
    int b = blockIdx.x;
    if (b < ge) {
        int i = b * 256 + threadIdx.x;
        if (i < ne) { int p = atomicAdd(&g_ecur[esrc[i]], 1); g_ecsr[p] = i; }
    } else if (b < ge + gt) {
        int i = (b - ge) * 256 + threadIdx.x;
        if (i < nt) { int p = atomicAdd(&g_tcur[ca[i]], 1); g_tcsr[p] = i; }
    } else if (b < ge + gt + ga) {
        __shared__ float W[64];
        if (threadIdx.x < 64) W[threadIdx.x] = Wda0[threadIdx.x];
        __syncthreads();
        int e = (b - ge - gt) * 256 + threadIdx.x;
        if (e < nea) da_one(W, g_da0, e);
    } else {
        __shared__ float W[64];
        if (threadIdx.x < 64) W[threadIdx.x] = Wda1[threadIdx.x];
        __syncthreads();
        int e = (b - ge - gt - ga) * 256 + threadIdx.x;
        if (e < nea) da_one(W, g_da1, e);
    }
}

// ---------------- layer 1: s = xi @ W_si1 ----------------
__global__ __launch_bounds__(128) void k_s1(const float* __restrict__ Wsi, int n) {
    __shared__ __align__(16) float Ws[64 * 96];   // 24 KB, one of 4 k-tiles
    int tid = threadIdx.x;
    int a = blockIdx.x * 128 + tid;
    bool act = (a < n);
    const float* xr = g_xi + (size_t)(act ? a : 0) * 256;
    float acc[96];
#pragma unroll
    for (int j = 0; j < 96; ++j) acc[j] = 0.0f;
    for (int kt = 0; kt < 4; ++kt) {
        __syncthreads();
        for (int i = tid; i < 64 * 96; i += 128) Ws[i] = Wsi[kt * 64 * 96 + i];
        __syncthreads();
        for (int k = 0; k < 64; ++k) {
            float av = xr[kt * 64 + k];
#pragma unroll
            for (int q = 0; q < 24; ++q) {
                float4 w = *(const float4*)&Ws[k * 96 + 4 * q];
                acc[4 * q + 0] += av * w.x;
                acc[4 * q + 1] += av * w.y;
                acc[4 * q + 2] += av * w.z;
                acc[4 * q + 3] += av * w.w;
            }
        }
    }
    if (!act) return;
    float* er = g_ei1 + (size_t)a * 616;
#pragma unroll
    for (int q = 0; q < 16; ++q)
        ((float4*)(er + 256))[q] = make_float4(acc[4 * q], acc[4 * q + 1], acc[4 * q + 2], acc[4 * q + 3]);
#pragma unroll
    for (int q = 0; q < 8; ++q)
        ((float4*)(g_sdst + (size_t)a * 32))[q] =
            make_float4(acc[64 + 4 * q], acc[65 + 4 * q], acc[66 + 4 * q], acc[67 + 4 * q]);
}

// ---------------- edge aggregation body (R4: index CSR, indirect loads) ----------------
__device__ __forceinline__ void mi_body(const int* __restrict__ edge_dst,
                                        float* __restrict__ ei, int di, int off,
                                        int w, int lane) {
    int beg = g_ecnt[w], end = g_ecnt[w + 1];
    float a0 = 0, a1 = 0, a2 = 0, a3 = 0, a4 = 0, a5 = 0, a6 = 0, a7 = 0;
#pragma unroll 2
    for (int idx = beg; idx < end; ++idx) {
        int e = g_ecsr[idx];
        int d = edge_dst[e];
        float4 r0 = *(const float4*)(g_rb + (size_t)e * 8);
        float4 r1 = *(const float4*)(g_rb + (size_t)e * 8 + 4);
        float v = g_sdst[(size_t)d * 32 + lane];
        a0 += r0.x * v; a1 += r0.y * v; a2 += r0.z * v; a3 += r0.w * v;
        a4 += r1.x * v; a5 += r1.y * v; a6 += r1.z * v; a7 += r1.w * v;
    }
    float* er = ei + (size_t)w * di + off;
    er[0 * 32 + lane] = a0; er[1 * 32 + lane] = a1; er[2 * 32 + lane] = a2; er[3 * 32 + lane] = a3;
    er[4 * 32 + lane] = a4; er[5 * 32 + lane] = a5; er[6 * 32 + lane] = a6; er[7 * 32 + lane] = a7;
}

// ---------------- triplet aggregation body (R4 form) ----------------
__device__ __forceinline__ void ami_body(const float* __restrict__ angles,
                                         const int* __restrict__ asrc,
                                         const int* __restrict__ adst,
                                         const float* __restrict__ da,
                                         float* __restrict__ ei, int di, int off,
                                         int w, int lane) {
    int beg = g_tcnt[w], end = g_tcnt[w + 1];
    float acc[40];
#pragma unroll
    for (int j = 0; j < 40; ++j) acc[j] = 0.0f;
    for (int idx = beg + lane; idx < end; idx += 32) {
        int t = g_tcsr[idx];
        float th = angles[t];
        int es = asrc[t], ed = adst[t];
        float4 s0 = *(const float4*)(da + (size_t)es * 8);
        float4 s1 = *(const float4*)(da + (size_t)es * 8 + 4);
        float4 d0 = *(const float4*)(da + (size_t)ed * 8);
        float4 d1 = *(const float4*)(da + (size_t)ed * 8 + 4);
        float dij[8] = { s0.x * d0.x, s0.y * d0.y, s0.z * d0.z, s0.w * d0.w,
                         s1.x * d1.x, s1.y * d1.y, s1.z * d1.z, s1.w * d1.w };
        float c = cosf(th);
        float xa[5];
        xa[0] = 1.0f; xa[1] = c;
#pragma unroll
        for (int m = 2; m < 5; ++m) xa[m] = 2.0f * c * xa[m - 1] - xa[m - 2];
#pragma unroll
        for (int m = 0; m < 5; ++m)
#pragma unroll
            for (int k = 0; k < 8; ++k)
                acc[m * 8 + k] += xa[m] * dij[k];
    }
#pragma unroll
    for (int j = 0; j < 40; ++j) {
        float v = acc[j];
        v += __shfl_down_sync(0xffffffffu, v, 16);
        v += __shfl_down_sync(0xffffffffu, v, 8);
        v += __shfl_down_sync(0xffffffffu, v, 4);
        v += __shfl_down_sync(0xffffffffu, v, 2);
        v += __shfl_down_sync(0xffffffffu, v, 1);
        acc[j] = v;
    }
    if (lane == 0) {
        float* er = ei + (size_t)w * di + off;
#pragma unroll
        for (int j = 0; j < 40; ++j) er[j] = acc[j];
    }
}

// ---------------- fused aggregation: mi0 + ami0 + ami1 (all independent) ----------------
__global__ void k_agg0(const int* __restrict__ edge_dst, const float* __restrict__ angles,
                       const int* __restrict__ asrc, const int* __restrict__ adst,
                       int n, int gm) {
    int b = blockIdx.x;
    int lane = threadIdx.x & 31;
    int wl = threadIdx.x >> 5;
    if (b < gm) {
        int w = b * 8 + wl;
        if (w < n) mi_body(edge_dst, g_ei0, 376, 80, w, lane);
    } else if (b < 2 * gm) {
        int w = (b - gm) * 8 + wl;
        if (w < n) ami_body(angles, asrc, adst, g_da0, g_ei0, 376, 336, w, lane);
    } else {
        int w = (b - 2 * gm) * 8 + wl;
        if (w < n) ami_body(angles, asrc, adst, g_da1, g_ei1, 616, 576, w, lane);
    }
}

// ---------------- layer-1 mi (after s1) ----------------
__global__ void k_mi1(const int* __restrict__ edge_dst, int n) {
    int w = (blockIdx.x * blockDim.x + threadIdx.x) >> 5;
    int lane = threadIdx.x & 31;
    if (w < n) mi_body(edge_dst, g_ei1, 616, 320, w, lane);
}

// ---------------- mix GEMM: out = tssr2(ei @ W + b) (+ xi residual) ----------------
// Tile: 96 atoms x 256 cols, 384 threads (12 warps), occ 1.
// Warp -> 8 atoms, lane -> 4 col-pairs (balanced 0.5 smem-wf per FFMA2).
// Grid = ceil(N/96) = 261 -> 1.76 waves @ 148 slots -> ceil 2, util 88%.
// layer==0: ei=g_ei0 (di=376), write g_xi AND copy into g_ei1[0:256].
// layer==1: ei=g_ei1 (di=616), residual + write out.
__global__ __launch_bounds__(384) void k_mix(const float* __restrict__ W,
                                             const float* __restrict__ bias,
                                             int layer, float* __restrict__ out_param,
                                             int n) {
    __shared__ __align__(16) float  Wt[8 * 256];   // 8 KB
    __shared__ __align__(8)  float2 At[8 * 96];    // 6 KB, duplicated-A
    int tid = threadIdx.x, lane = tid & 31, w = tid >> 5;   // w in [0,12)
    int a0 = blockIdx.x * 96;
    const float* ei = layer ? g_ei1 : g_ei0;
    int di = layer ? 616 : 376;
    float* out = layer ? out_param : g_xi;

    unsigned long long acc[8][4];
#pragma unroll
    for (int i = 0; i < 8; ++i)
#pragma unroll
        for (int p = 0; p < 4; ++p) acc[i][p] = 0ull;

    int ktiles = di >> 3;
    for (int kt = 0; kt < ktiles; ++kt) {
        int k0 = kt << 3;
        {   // W tile: 8 rows x 256 cols = 512 float4 over 384 threads
            const float4* src = (const float4*)(W + (size_t)k0 * 256);
            float4* d4 = (float4*)Wt;
            d4[tid] = src[tid];
            if (tid < 128) d4[384 + tid] = src[384 + tid];
        }
        if (tid < 192) {  // A tile: 96 atoms x 8 ks, duplicated [kk][atom]
            int at = tid >> 1, half = tid & 1;
            int g = a0 + at; if (g >= n) g = n - 1;
            float4 v = *(const float4*)(ei + (size_t)g * di + k0 + half * 4);
            int bq = half * 4;
            At[(bq + 0) * 96 + at] = make_float2(v.x, v.x);
            At[(bq + 1) * 96 + at] = make_float2(v.y, v.y);
            At[(bq + 2) * 96 + at] = make_float2(v.z, v.z);
            At[(bq + 3) * 96 + at] = make_float2(v.w, v.w);
        }
        __syncthreads();
#pragma unroll
        for (int kk = 0; kk < 8; ++kk) {
            unsigned long long wv[4];
#pragma unroll
            for (int p = 0; p < 4; ++p)
                wv[p] = *(const unsigned long long*)&Wt[kk * 256 + 2 * (lane + 32 * p)];
#pragma unroll
            for (int i = 0; i < 8; ++i) {
                unsigned long long a2 = *(const unsigned long long*)&At[kk * 96 + w * 8 + i];
#pragma unroll
                for (int p = 0; p < 4; ++p) acc[i][p] = ffma2(a2, wv[p], acc[i][p]);
            }
        }
        __syncthreads();
    }

    float2 bv[4];
#pragma unroll
    for (int p = 0; p < 4; ++p) bv[p] = *(const float2*)&bias[2 * (lane + 32 * p)];
#pragma unroll
    for (int i = 0; i < 8; ++i) {
        int g = a0 + w * 8 + i;
        if (g >= n) continue;
#pragma unroll
        for (int p = 0; p < 4; ++p) {
            int col = 2 * (lane + 32 * p);
            float2 v;
            v.x = __uint_as_float((unsigned)(acc[i][p] & 0xffffffffull));
            v.y = __uint_as_float((unsigned)(acc[i][p] >> 32));
            v.x = tssr2f(v.x + bv[p].x);
            v.y = tssr2f(v.y + bv[p].y);
            if (layer) {
                float2 r = *(const float2*)&g_xi[(size_t)g * 256 + col];
                v.x += r.x; v.y += r.y;
                *(float2*)&out[(size_t)g * 256 + col] = v;
            } else {
                *(float2*)&out[(size_t)g * 256 + col] = v;
                // fused copy of xi into ei1[0:256]
                *(float2*)&g_ei1[(size_t)g * 616 + col] = v;
            }
        }
    }
}

// ---------------- launch ----------------
static inline int cdiv(int a, int b) { return (a + b - 1) / b; }

extern "C" void kernel_launch(void* const* d_in, const int* in_sizes, int n_in,
                              void* d_out, int out_size) {
    const int*   species   = (const int*)  d_in[0];
    const int*   edge_src  = (const int*)  d_in[1];
    const int*   edge_dst  = (const int*)  d_in[2];
    const float* distances = (const float*)d_in[3];
    const float* sw        = (const float*)d_in[4];
    const float* angles    = (const float*)d_in[5];
    const int*   angle_src = (const int*)  d_in[6];
    const int*   angle_dst = (const int*)  d_in[7];
    const int*   central   = (const int*)  d_in[8];
    const float* dist_a    = (const float*)d_in[9];
    const float* sw_a      = (const float*)d_in[10];
    const float* table     = (const float*)d_in[11];
    const float* W_si0     = (const float*)d_in[12];
    const float* W_si1     = (const float*)d_in[13];
    const float* W_da0     = (const float*)d_in[14];
    const float* W_da1     = (const float*)d_in[15];
    const float* W_mix0    = (const float*)d_in[16];
    const float* b_mix0    = (const float*)d_in[17];
    const float* W_mix1    = (const float*)d_in[18];
    const float* b_mix1    = (const float*)d_in[19];
    float* out = (float*)d_out;

    int N_  = in_sizes[0];
    int E_  = in_sizes[1];
    int T_  = in_sizes[5];
    int EA_ = in_sizes[9];

    int gs  = cdiv(N_, 256);
    int ge  = cdiv(E_, 256);
    int gt  = cdiv(T_, 256);
    int ga  = cdiv(EA_, 256);
    int gm  = cdiv(N_, 8);
    int gx  = cdiv(N_, 96);

    // 0) zero counters (must precede fused histograms)
    k_zero<<<gs, 256>>>(N_);
    // 1) s0 + both radial bases + both histograms (all independent)
    k_prep1<<<gs + ge + ga + ge + gt, 256>>>(species, table, W_si0,
                                             distances, sw, dist_a, sw_a,
                                             edge_src, central,
                                             N_, E_, EA_, T_, gs, ge, ga, ge);
    // 2) both scans
    k_scan2<<<2, 1024>>>(N_);
    // 3) both scatters + both da projections
    k_prep2<<<ge + gt + 2 * ga, 256>>>(edge_src, central, W_da0, W_da1,
                                       E_, T_, EA_, ge, gt, ga);
    // 4) mi0 + ami0 + ami1 (ami1 off the critical path)
    k_agg0<<<3 * gm, 256>>>(edge_dst, angles, angle_src, angle_dst, N_, gm);
    // 5) mix0 -> g_xi (+ fused copy into ei1[0:256])
    k_mix<<<gx, 384>>>(W_mix0, b_mix0, 0, nullptr, N_);
    // 6) layer-1 self projection
    k_s1<<<cdiv(N_, 128), 128>>>(W_si1, N_);
    // 7) layer-1 edge aggregation
    k_mi1<<<gm, 256>>>(edge_dst, N_);
    // 8) mix1 -> out (residual)
    k_mix<<<gx, 384>>>(W_mix1, b_mix1, 1, out, N_);
}

// round 10
// speedup vs baseline: 1.3152x; 1.3152x over previous
#include <cuda_runtime.h>
#include <cstdint>
#include <cstddef>

// ---------------- problem-size caps (from reference) ----------------
#define NMAXA  25000
#define EMAXE  800000
#define EAMAXE 300000
#define TMAXT  1600000

// ---------------- static device scratch (no allocations) ----------------
__device__ float g_rb  [EMAXE  * 8];              // radial basis per edge
__device__ float g_rba [EAMAXE * 8];              // radial basis per angle-edge
__device__ float g_da0 [EAMAXE * 8];              // rba @ W_da0
__device__ float g_da1 [EAMAXE * 8];              // rba @ W_da1
__device__ float g_sdst[NMAXA  * 32];             // s[:,64:96] per atom (per layer)
__device__ float g_ei0 [(size_t)NMAXA * 376];     // layer-0 concat features
__device__ float g_ei1 [(size_t)NMAXA * 616];     // layer-1 concat features
__device__ float g_xi  [(size_t)NMAXA * 256];     // atom state after layer 0
__device__ int   g_etmp[NMAXA];
__device__ int   g_ttmp[NMAXA];
__device__ int   g_ecnt[NMAXA + 1];
__device__ int   g_tcnt[NMAXA + 1];
__device__ int   g_ecur[NMAXA];
__device__ int   g_tcur[NMAXA];
__device__ int   g_ecsr[EMAXE];
__device__ int   g_tcsr[TMAXT];

#define PI_F 3.14159265358979323846f

// ---------------- helpers ----------------
__device__ __forceinline__ unsigned long long ffma2(unsigned long long a,
                                                    unsigned long long b,
                                                    unsigned long long c) {
    unsigned long long d;
    asm("fma.rn.f32x2 %0, %1, %2, %3;" : "=l"(d) : "l"(a), "l"(b), "l"(c));
    return d;
}

__device__ __forceinline__ float tssr2f(float x) {
    float ax = fabsf(x);
    if (ax <= 1.0f) return x;
    return copysignf(2.0f * sqrtf(ax) - 1.0f, x);
}

// ---------------- radial bessel basis * switch (per element) ----------------
__device__ __forceinline__ void radial_one(const float* __restrict__ dist,
                                           const float* __restrict__ sw,
                                           float* __restrict__ out, int e, float rc) {
    float r = dist[e], w = sw[e];
    float x = (PI_F / rc) * r;
    float s, c;
    sincosf(x, &s, &c);
    float norm = sqrtf(2.0f / rc) * w / r;
    float c2 = 2.0f * c;
    float o[8];
    float sk = s, skm = 0.0f;
#pragma unroll
    for (int k = 0; k < 8; ++k) {
        o[k] = sk * norm;
        float nx = c2 * sk - skm;
        skm = sk; sk = nx;
    }
    float4* dst = (float4*)(out + (size_t)e * 8);
    dst[0] = make_float4(o[0], o[1], o[2], o[3]);
    dst[1] = make_float4(o[4], o[5], o[6], o[7]);
}

// ---------------- s0 body: species_table[species] @ W_si0 ----------------
__device__ __forceinline__ void s0_body(const int* __restrict__ species,
                                        const float* __restrict__ table,
                                        const float* __restrict__ Wsi,
                                        int n, int blk) {
    __shared__ __align__(16) float Ws[16 * 96];
    for (int i = threadIdx.x; i < 16 * 96; i += 256) Ws[i] = Wsi[i];
    __syncthreads();
    int a = blk * 256 + threadIdx.x;
    if (a >= n) return;
    int sp = species[a];
    float* er = g_ei0 + (size_t)a * 376;
    float xv[16];
#pragma unroll
    for (int q = 0; q < 4; ++q) {
        float4 t = ((const float4*)(table + (size_t)sp * 16))[q];
        xv[4 * q + 0] = t.x; xv[4 * q + 1] = t.y; xv[4 * q + 2] = t.z; xv[4 * q + 3] = t.w;
        ((float4*)er)[q] = t;
    }
    float acc[96];
#pragma unroll
    for (int j = 0; j < 96; ++j) acc[j] = 0.0f;
#pragma unroll
    for (int k = 0; k < 16; ++k) {
        float av = xv[k];
#pragma unroll
        for (int q = 0; q < 24; ++q) {
            float4 w = *(const float4*)&Ws[k * 96 + 4 * q];
            acc[4 * q + 0] += av * w.x;
            acc[4 * q + 1] += av * w.y;
            acc[4 * q + 2] += av * w.z;
            acc[4 * q + 3] += av * w.w;
        }
    }
#pragma unroll
    for (int q = 0; q < 16; ++q)
        ((float4*)(er + 16))[q] = make_float4(acc[4 * q], acc[4 * q + 1], acc[4 * q + 2], acc[4 * q + 3]);
#pragma unroll
    for (int q = 0; q < 8; ++q)
        ((float4*)(g_sdst + (size_t)a * 32))[q] =
            make_float4(acc[64 + 4 * q], acc[65 + 4 * q], acc[66 + 4 * q], acc[67 + 4 * q]);
}

// ---------------- fused prep 1: s0 + zero counters + rb + rba ----------------
__global__ __launch_bounds__(256) void k_prep1(
        const int* __restrict__ species, const float* __restrict__ table,
        const float* __restrict__ Wsi0,
        const float* __restrict__ dist, const float* __restrict__ sw,
        const float* __restrict__ dist_a, const float* __restrict__ sw_a,
        int n_atoms, int ne, int nea, int gs, int gz, int ge) {
    int b = blockIdx.x;
    if (b < gs) {
        s0_body(species, table, Wsi0, n_atoms, b);
    } else if (b < gs + gz) {
        int i = (b - gs) * 256 + threadIdx.x;
        if (i < n_atoms) { g_etmp[i] = 0; g_ttmp[i] = 0; }
    } else if (b < gs + gz + ge) {
        int e = (b - gs - gz) * 256 + threadIdx.x;
        if (e < ne) radial_one(dist, sw, g_rb, e, 5.0f);
    } else {
        int e = (b - gs - gz - ge) * 256 + threadIdx.x;
        if (e < nea) radial_one(dist_a, sw_a, g_rba, e, 3.5f);
    }
}

// ---------------- fused histograms ----------------
__global__ void k_hist(const int* __restrict__ esrc, const int* __restrict__ ca,
                       int ne, int nt, int ge) {
    int b = blockIdx.x;
    if (b < ge) {
        int i = b * 256 + threadIdx.x;
        if (i < ne) atomicAdd(&g_etmp[esrc[i]], 1);
    } else {
        int i = (b - ge) * 256 + threadIdx.x;
        if (i < nt) atomicAdd(&g_ttmp[ca[i]], 1);
    }
}

// ---------------- both scans in one launch (shfl-based, 2 blocks) ----------------
__device__ __forceinline__ void scan_body(const int* __restrict__ cnt,
                                          int* __restrict__ offs,
                                          int* __restrict__ cur, int n) {
    __shared__ int wsum[32];
    __shared__ int s_carry;
    int tid = threadIdx.x, lane = tid & 31, wid = tid >> 5;
    if (tid == 0) s_carry = 0;
    __syncthreads();
    for (int base = 0; base < n; base += 1024) {
        int v = (base + tid < n) ? cnt[base + tid] : 0;
        int x = v;
#pragma unroll
        for (int o = 1; o < 32; o <<= 1) {
            int t = __shfl_up_sync(0xffffffffu, x, o);
            if (lane >= o) x += t;
        }
        if (lane == 31) wsum[wid] = x;
        __syncthreads();
        if (wid == 0) {
            int y = wsum[lane];
#pragma unroll
            for (int o = 1; o < 32; o <<= 1) {
                int t = __shfl_up_sync(0xffffffffu, y, o);
                if (lane >= o) y += t;
            }
            wsum[lane] = y;
        }
        __syncthreads();
        int woff = wid ? wsum[wid - 1] : 0;
        int carry = s_carry;
        int total = wsum[31];
        int excl = carry + woff + x - v;
        if (base + tid < n) { offs[base + tid] = excl; cur[base + tid] = excl; }
        __syncthreads();
        if (tid == 0) s_carry = carry + total;
        __syncthreads();
    }
    if (tid == 0) offs[n] = s_carry;
}

__global__ void k_scan2(int n) {
    if (blockIdx.x == 0) scan_body(g_etmp, g_ecnt, g_ecur, n);
    else                 scan_body(g_ttmp, g_tcnt, g_tcur, n);
}

// ---------------- fused prep 2: scatter_e + scatter_t + da0 + da1 ----------------
__device__ __forceinline__ void da_one(const float* __restrict__ Wsh,
                                       float* __restrict__ out, int e) {
    float4 r0 = *(const float4*)(g_rba + (size_t)e * 8);
    float4 r1 = *(const float4*)(g_rba + (size_t)e * 8 + 4);
    float r[8] = { r0.x, r0.y, r0.z, r0.w, r1.x, r1.y, r1.z, r1.w };
    float o[8];
#pragma unroll
    for (int j = 0; j < 8; ++j) {
        float s = 0.0f;
#pragma unroll
        for (int k = 0; k < 8; ++k) s += r[k] * Wsh[k * 8 + j];
        o[j] = s;
    }
    float4* dst = (float4*)(out + (size_t)e * 8);
    dst[0] = make_float4(o[0], o[1], o[2], o[3]);
    dst[1] = make_float4(o[4], o[5], o[6], o[7]);
}

__global__ void k_prep2(const int* __restrict__ esrc, const int* __restrict__ ca,
                        const float* __restrict__ Wda0, const float* __restrict__ Wda1,
                        int ne, int nt, int nea, int ge, int gt, int ga) {
    int b = blockIdx.x;
    if (b < ge) {
        int i = b * 256 + threadIdx.x;
        if (i < ne) { int p = atomicAdd(&g_ecur[esrc[i]], 1); g_ecsr[p] = i; }
    } else if (b < ge + gt) {
        int i = (b - ge) * 256 + threadIdx.x;
        if (i < nt) { int p = atomicAdd(&g_tcur[ca[i]], 1); g_tcsr[p] = i; }
    } else if (b < ge + gt + ga) {
        __shared__ float W[64];
        if (threadIdx.x < 64) W[threadIdx.x] = Wda0[threadIdx.x];
        __syncthreads();
        int e = (b - ge - gt) * 256 + threadIdx.x;
        if (e < nea) da_one(W, g_da0, e);
    } else {
        __shared__ float W[64];
        if (threadIdx.x < 64) W[threadIdx.x] = Wda1[threadIdx.x];
        __syncthreads();
        int e = (b - ge - gt - ga) * 256 + threadIdx.x;
        if (e < nea) da_one(W, g_da1, e);
    }
}

// ---------------- layer 1: s = xi @ W_si1 ----------------
__global__ __launch_bounds__(128) void k_s1(const float* __restrict__ Wsi, int n) {
    __shared__ __align__(16) float Ws[64 * 96];   // 24 KB, one of 4 k-tiles
    int tid = threadIdx.x;
    int a = blockIdx.x * 128 + tid;
    bool act = (a < n);
    const float* xr = g_xi + (size_t)(act ? a : 0) * 256;
    float acc[96];
#pragma unroll
    for (int j = 0; j < 96; ++j) acc[j] = 0.0f;
    for (int kt = 0; kt < 4; ++kt) {
        __syncthreads();
        for (int i = tid; i < 64 * 96; i += 128) Ws[i] = Wsi[kt * 64 * 96 + i];
        __syncthreads();
        for (int k = 0; k < 64; ++k) {
            float av = xr[kt * 64 + k];
#pragma unroll
            for (int q = 0; q < 24; ++q) {
                float4 w = *(const float4*)&Ws[k * 96 + 4 * q];
                acc[4 * q + 0] += av * w.x;
                acc[4 * q + 1] += av * w.y;
                acc[4 * q + 2] += av * w.z;
                acc[4 * q + 3] += av * w.w;
            }
        }
    }
    if (!act) return;
    float* er = g_ei1 + (size_t)a * 616;
#pragma unroll
    for (int q = 0; q < 16; ++q)
        ((float4*)(er + 256))[q] = make_float4(acc[4 * q], acc[4 * q + 1], acc[4 * q + 2], acc[4 * q + 3]);
#pragma unroll
    for (int q = 0; q < 8; ++q)
        ((float4*)(g_sdst + (size_t)a * 32))[q] =
            make_float4(acc[64 + 4 * q], acc[65 + 4 * q], acc[66 + 4 * q], acc[67 + 4 * q]);
}

// ---------------- edge aggregation body ----------------
__device__ __forceinline__ void mi_body(const int* __restrict__ edge_dst,
                                        float* __restrict__ ei, int di, int off,
                                        int w, int lane) {
    int beg = g_ecnt[w], end = g_ecnt[w + 1];
    float a0 = 0, a1 = 0, a2 = 0, a3 = 0, a4 = 0, a5 = 0, a6 = 0, a7 = 0;
#pragma unroll 2
    for (int idx = beg; idx < end; ++idx) {
        int e = g_ecsr[idx];
        int d = edge_dst[e];
        float4 r0 = *(const float4*)(g_rb + (size_t)e * 8);
        float4 r1 = *(const float4*)(g_rb + (size_t)e * 8 + 4);
        float v = g_sdst[(size_t)d * 32 + lane];
        a0 += r0.x * v; a1 += r0.y * v; a2 += r0.z * v; a3 += r0.w * v;
        a4 += r1.x * v; a5 += r1.y * v; a6 += r1.z * v; a7 += r1.w * v;
    }
    float* er = ei + (size_t)w * di + off;
    er[0 * 32 + lane] = a0; er[1 * 32 + lane] = a1; er[2 * 32 + lane] = a2; er[3 * 32 + lane] = a3;
    er[4 * 32 + lane] = a4; er[5 * 32 + lane] = a5; er[6 * 32 + lane] = a6; er[7 * 32 + lane] = a7;
}

// ---------------- triplet aggregation body ----------------
__device__ __forceinline__ void ami_body(const float* __restrict__ angles,
                                         const int* __restrict__ asrc,
                                         const int* __restrict__ adst,
                                         const float* __restrict__ da,
                                         float* __restrict__ ei, int di, int off,
                                         int w, int lane) {
    int beg = g_tcnt[w], end = g_tcnt[w + 1];
    float acc[40];
#pragma unroll
    for (int j = 0; j < 40; ++j) acc[j] = 0.0f;
    for (int idx = beg + lane; idx < end; idx += 32) {
        int t = g_tcsr[idx];
        float th = angles[t];
        int es = asrc[t], ed = adst[t];
        float4 s0 = *(const float4*)(da + (size_t)es * 8);
        float4 s1 = *(const float4*)(da + (size_t)es * 8 + 4);
        float4 d0 = *(const float4*)(da + (size_t)ed * 8);
        float4 d1 = *(const float4*)(da + (size_t)ed * 8 + 4);
        float dij[8] = { s0.x * d0.x, s0.y * d0.y, s0.z * d0.z, s0.w * d0.w,
                         s1.x * d1.x, s1.y * d1.y, s1.z * d1.z, s1.w * d1.w };
        float c = cosf(th);
        float xa[5];
        xa[0] = 1.0f; xa[1] = c;
#pragma unroll
        for (int m = 2; m < 5; ++m) xa[m] = 2.0f * c * xa[m - 1] - xa[m - 2];
#pragma unroll
        for (int m = 0; m < 5; ++m)
#pragma unroll
            for (int k = 0; k < 8; ++k)
                acc[m * 8 + k] += xa[m] * dij[k];
    }
#pragma unroll
    for (int j = 0; j < 40; ++j) {
        float v = acc[j];
        v += __shfl_down_sync(0xffffffffu, v, 16);
        v += __shfl_down_sync(0xffffffffu, v, 8);
        v += __shfl_down_sync(0xffffffffu, v, 4);
        v += __shfl_down_sync(0xffffffffu, v, 2);
        v += __shfl_down_sync(0xffffffffu, v, 1);
        acc[j] = v;
    }
    if (lane == 0) {
        float* er = ei + (size_t)w * di + off;
#pragma unroll
        for (int j = 0; j < 40; ++j) er[j] = acc[j];
    }
}

// ---------------- fused aggregation: mi0 + ami0 + ami1 (all independent) ----------------
__global__ void k_agg0(const int* __restrict__ edge_dst, const float* __restrict__ angles,
                       const int* __restrict__ asrc, const int* __restrict__ adst,
                       int n, int gm) {
    int b = blockIdx.x;
    int lane = threadIdx.x & 31;
    int wl = threadIdx.x >> 5;
    if (b < gm) {
        int w = b * 8 + wl;
        if (w < n) mi_body(edge_dst, g_ei0, 376, 80, w, lane);
    } else if (b < 2 * gm) {
        int w = (b - gm) * 8 + wl;
        if (w < n) ami_body(angles, asrc, adst, g_da0, g_ei0, 376, 336, w, lane);
    } else {
        int w = (b - 2 * gm) * 8 + wl;
        if (w < n) ami_body(angles, asrc, adst, g_da1, g_ei1, 616, 576, w, lane);
    }
}

// ---------------- layer-1 mi (after s1) ----------------
__global__ void k_mi1(const int* __restrict__ edge_dst, int n) {
    int w = (blockIdx.x * blockDim.x + threadIdx.x) >> 5;
    int lane = threadIdx.x & 31;
    if (w < n) mi_body(edge_dst, g_ei1, 616, 320, w, lane);
}

// ---------------- mix GEMM: out = tssr2(ei @ W + b) (+ xi residual) ----------------
// CTA: 64 atoms x 256 cols, 256 threads, occ 2 (the proven R4 shape),
// now with register-staged DOUBLE-BUFFERED smem: one __syncthreads per k-tile,
// next tile's global loads in flight under the FMA loop.
// layer==0: ei=g_ei0 (di=376), write g_xi AND copy into g_ei1[0:256].
// layer==1: ei=g_ei1 (di=616), residual + write out.
__global__ __launch_bounds__(256, 2) void k_mix(const float* __restrict__ W,
                                                const float* __restrict__ bias,
                                                int layer, float* __restrict__ out_param,
                                                int n) {
    __shared__ __align__(16) float  Wt[2][8 * 256];   // 2 x 8 KB
    __shared__ __align__(8)  float2 At[2][8 * 64];    // 2 x 4 KB, duplicated-A
    int tid = threadIdx.x, lane = tid & 31, w = tid >> 5;
    int a0 = blockIdx.x * 64;
    const float* ei = layer ? g_ei1 : g_ei0;
    int di = layer ? 616 : 376;
    float* out = layer ? out_param : g_xi;

    unsigned long long acc[8][4];
#pragma unroll
    for (int i = 0; i < 8; ++i)
#pragma unroll
        for (int p = 0; p < 4; ++p) acc[i][p] = 0ull;

    int ktiles = di >> 3;
    const float4* wsrc = (const float4*)W;            // [di][256] floats = [di*64] float4
    int at = tid >> 1, half = tid & 1;
    int gA = a0 + at; if (gA >= n) gA = n - 1;
    bool aload = (tid < 128);
    const float4* arow = (const float4*)(ei + (size_t)gA * di + half * 4);

    // prologue: stage tile 0 in registers
    float4 rw0 = wsrc[tid];
    float4 rw1 = wsrc[tid + 256];
    float4 ra;
    if (aload) ra = arow[0];

    for (int kt = 0; kt < ktiles; ++kt) {
        int b = kt & 1;
        // commit staged tile to smem buffer b
        ((float4*)Wt[b])[tid]       = rw0;
        ((float4*)Wt[b])[tid + 256] = rw1;
        if (aload) {
            int bq = half * 4;
            At[b][(bq + 0) * 64 + at] = make_float2(ra.x, ra.x);
            At[b][(bq + 1) * 64 + at] = make_float2(ra.y, ra.y);
            At[b][(bq + 2) * 64 + at] = make_float2(ra.z, ra.z);
            At[b][(bq + 3) * 64 + at] = make_float2(ra.w, ra.w);
        }
        // issue next tile's global loads (in flight during compute below)
        if (kt + 1 < ktiles) {
            size_t wo = (size_t)(kt + 1) * 512;
            rw0 = wsrc[wo + tid];
            rw1 = wsrc[wo + tid + 256];
            if (aload) ra = arow[(size_t)(kt + 1) * 2];   // +8 floats = +2 float4
        }
        __syncthreads();
#pragma unroll
        for (int kk = 0; kk < 8; ++kk) {
            unsigned long long wv[4];
#pragma unroll
            for (int p = 0; p < 4; ++p)
                wv[p] = *(const unsigned long long*)&Wt[b][kk * 256 + 2 * (lane + 32 * p)];
#pragma unroll
            for (int i = 0; i < 8; ++i) {
                unsigned long long a2 = *(const unsigned long long*)&At[b][kk * 64 + w * 8 + i];
#pragma unroll
                for (int p = 0; p < 4; ++p) acc[i][p] = ffma2(a2, wv[p], acc[i][p]);
            }
        }
    }

    float2 bv[4];
#pragma unroll
    for (int p = 0; p < 4; ++p) bv[p] = *(const float2*)&bias[2 * (lane + 32 * p)];
#pragma unroll
    for (int i = 0; i < 8; ++i) {
        int g = a0 + w * 8 + i;
        if (g >= n) continue;
#pragma unroll
        for (int p = 0; p < 4; ++p) {
            int col = 2 * (lane + 32 * p);
            float2 v;
            v.x = __uint_as_float((unsigned)(acc[i][p] & 0xffffffffull));
            v.y = __uint_as_float((unsigned)(acc[i][p] >> 32));
            v.x = tssr2f(v.x + bv[p].x);
            v.y = tssr2f(v.y + bv[p].y);
            if (layer) {
                float2 r = *(const float2*)&g_xi[(size_t)g * 256 + col];
                v.x += r.x; v.y += r.y;
                *(float2*)&out[(size_t)g * 256 + col] = v;
            } else {
                *(float2*)&out[(size_t)g * 256 + col] = v;
                // fused copy of xi into ei1[0:256]
                *(float2*)&g_ei1[(size_t)g * 616 + col] = v;
            }
        }
    }
}

// ---------------- launch ----------------
static inline int cdiv(int a, int b) { return (a + b - 1) / b; }

extern "C" void kernel_launch(void* const* d_in, const int* in_sizes, int n_in,
                              void* d_out, int out_size) {
    const int*   species   = (const int*)  d_in[0];
    const int*   edge_src  = (const int*)  d_in[1];
    const int*   edge_dst  = (const int*)  d_in[2];
    const float* distances = (const float*)d_in[3];
    const float* sw        = (const float*)d_in[4];
    const float* angles    = (const float*)d_in[5];
    const int*   angle_src = (const int*)  d_in[6];
    const int*   angle_dst = (const int*)  d_in[7];
    const int*   central   = (const int*)  d_in[8];
    const float* dist_a    = (const float*)d_in[9];
    const float* sw_a      = (const float*)d_in[10];
    const float* table     = (const float*)d_in[11];
    const float* W_si0     = (const float*)d_in[12];
    const float* W_si1     = (const float*)d_in[13];
    const float* W_da0     = (const float*)d_in[14];
    const float* W_da1     = (const float*)d_in[15];
    const float* W_mix0    = (const float*)d_in[16];
    const float* b_mix0    = (const float*)d_in[17];
    const float* W_mix1    = (const float*)d_in[18];
    const float* b_mix1    = (const float*)d_in[19];
    float* out = (float*)d_out;

    int N_  = in_sizes[0];
    int E_  = in_sizes[1];
    int T_  = in_sizes[5];
    int EA_ = in_sizes[9];

    int gs = cdiv(N_, 256);
    int gz = cdiv(N_, 256);
    int ge = cdiv(E_, 256);
    int gt = cdiv(T_, 256);
    int ga = cdiv(EA_, 256);
    int gm = cdiv(N_, 8);
    int gx = cdiv(N_, 64);

    // 1) s0 + zero counters + both radial bases (all independent)
    k_prep1<<<gs + gz + ge + ga, 256>>>(species, table, W_si0,
                                        distances, sw, dist_a, sw_a,
                                        N_, E_, EA_, gs, gz, ge);
    // 2) both histograms
    k_hist<<<ge + gt, 256>>>(edge_src, central, E_, T_, ge);
    // 3) both scans
    k_scan2<<<2, 1024>>>(N_);
    // 4) both scatters + both da projections
    k_prep2<<<ge + gt + 2 * ga, 256>>>(edge_src, central, W_da0, W_da1,
                                       E_, T_, EA_, ge, gt, ga);
    // 5) mi0 + ami0 + ami1 (ami1 off the critical path)
    k_agg0<<<3 * gm, 256>>>(edge_dst, angles, angle_src, angle_dst, N_, gm);
    // 6) mix0 -> g_xi (+ fused copy into ei1[0:256])
    k_mix<<<gx, 256>>>(W_mix0, b_mix0, 0, nullptr, N_);
    // 7) layer-1 self projection
    k_s1<<<cdiv(N_, 128), 128>>>(W_si1, N_);
    // 8) layer-1 edge aggregation
    k_mi1<<<gm, 256>>>(edge_dst, N_);
    // 9) mix1 -> out (residual)
    k_mix<<<gx, 256>>>(W_mix1, b_mix1, 1, out, N_);
}